// round 9
// baseline (speedup 1.0000x reference)
#include <cuda_runtime.h>
#include <cuda_bf16.h>
#include <math.h>

// Problem constants
#define BB   8
#define CC   256
#define HW   40000          // 200*200
#define HW4  10000          // HW / 4
#define KK   8000           // int(0.2 * HW)
#define NB16 65536           // 16-bit key histogram bins

// Scratch (allocation-free rule: __device__ globals)
__device__ unsigned g_score_u[BB * HW];    // float bits of sum(x^2) (>=0: uint order == float order)
__device__ float    g_sim[BB * HW];        // per-pixel cosine similarity
__device__ unsigned g_hist16[BB * NB16];   // per-batch histogram of (score_bits >> 16); zero-init, consume-and-clear
__device__ double   g_bsum[BB];            // per-batch sum of selected sims
__device__ unsigned g_done;                // completion counter (reset by last block)

// ---------------------------------------------------------------------------
// Kernel 1: fused per-pixel channel statistics -> score + cosine sim,
// PLUS a global 16-bit-key score histogram (spread REDG atomics hidden
// under the DRAM-bound stream). grid=1250 x block=64 (104us @ DRAM 80%).
// ---------------------------------------------------------------------------
__global__ void __launch_bounds__(64) k_stats(const float* __restrict__ bev,
                                              const float* __restrict__ pri) {
    int idx = blockIdx.x * 64 + threadIdx.x;   // 1250*64 = 80000 exact
    int b  = idx / HW4;
    int p4 = idx - b * HW4;

    const float4* pb = reinterpret_cast<const float4*>(bev + (size_t)b * CC * HW) + p4;
    const float4* pp = reinterpret_cast<const float4*>(pri + (size_t)b * CC * HW) + p4;

    float4 sb  = {0.f, 0.f, 0.f, 0.f};
    float4 sp  = {0.f, 0.f, 0.f, 0.f};
    float4 sbb = {0.f, 0.f, 0.f, 0.f};
    float4 spp = {0.f, 0.f, 0.f, 0.f};
    float4 sbp = {0.f, 0.f, 0.f, 0.f};

#pragma unroll 4
    for (int c = 0; c < CC; c++) {
        float4 x = __ldg(pb + c * HW4);
        float4 y = __ldg(pp + c * HW4);
#define ACC(f)                                \
        sb.f  += x.f;                         \
        sp.f  += y.f;                         \
        sbb.f  = fmaf(x.f, x.f, sbb.f);       \
        spp.f  = fmaf(y.f, y.f, spp.f);       \
        sbp.f  = fmaf(x.f, y.f, sbp.f);
        ACC(x) ACC(y) ACC(z) ACC(w)
#undef ACC
    }

    const float invC  = 1.0f / (float)CC;
    const float invC1 = 1.0f / (float)(CC - 1);
    int obase = b * HW + p4 * 4;
    unsigned* hist = g_hist16 + b * NB16;

#define EMIT(f, j) {                                                        \
        float Sb = sb.f, Sp = sp.f, Sb2 = sbb.f, Sp2 = spp.f, Sxp = sbp.f;  \
        float SSb = fmaxf(Sb2 - Sb * Sb * invC, 0.0f);                      \
        float SSp = fmaxf(Sp2 - Sp * Sp * invC, 0.0f);                      \
        float Cov = Sxp - Sb * Sp * invC;                                   \
        float sgb = sqrtf(SSb * invC1) + 1e-6f;                             \
        float sgp = sqrtf(SSp * invC1) + 1e-6f;                             \
        float na  = sqrtf(SSb) / sgb;                                       \
        float nb  = sqrtf(SSp) / sgp;                                       \
        float sim = (Cov / (sgb * sgp)) /                                   \
                    (fmaxf(na, 1e-8f) * fmaxf(nb, 1e-8f));                  \
        unsigned su = __float_as_uint(Sb2);                                 \
        g_score_u[obase + j] = su;                                          \
        g_sim[obase + j]     = sim;                                         \
        atomicAdd(&hist[su >> 16], 1u);                                     \
    }
    EMIT(x, 0) EMIT(y, 1) EMIT(z, 2) EMIT(w, 3)
#undef EMIT
}

// ---------------------------------------------------------------------------
// Kernel 2: per-batch exact top-k threshold + sim sum + FUSED finalize.
// One block per batch. Consume-and-clear of the histogram keeps graph
// replays valid without a zeroing kernel; fence+counter lets the last
// block compute the scalar loss (no finalize kernel).
// ---------------------------------------------------------------------------
__global__ void __launch_bounds__(1024) k_select_sum(const float* __restrict__ dx,
                                                     const float* __restrict__ dy,
                                                     const float* __restrict__ dt,
                                                     float* __restrict__ out) {
    extern __shared__ unsigned sc[];     // 40000 score words (160 KB)
    int b = blockIdx.x;
    const uint4*  s4   = reinterpret_cast<const uint4*>(g_score_u + b * HW);
    const float4* sim4 = reinterpret_cast<const float4*>(g_sim + b * HW);
    unsigned* hist = g_hist16 + b * NB16;
    uint4* sc4 = reinterpret_cast<uint4*>(sc);

    __shared__ unsigned chunk[1024];     // per-thread 64-bin sums -> suffix scan
    __shared__ unsigned h256[256];
    __shared__ unsigned sh_B16, sh_T;
    __shared__ int sh_k1, sh_k2, sh_needed, sh_tie;
    __shared__ float red[32];

    const int tid  = threadIdx.x;
    const int lane = tid & 31;
    const int wid  = tid >> 5;

    if (tid == 0) sh_tie = 0;

    // ---- load all scores into smem (coalesced uint4, independent loads) ----
    for (int i = tid; i < HW4; i += 1024)
        sc4[i] = s4[i];

    // ---- Stage A: chunk sums of the 16-bit histogram (64 bins/thread) ----
    {
        const uint4* h4 = reinterpret_cast<const uint4*>(hist) + tid * 16;
        unsigned t = 0;
#pragma unroll
        for (int i = 0; i < 16; i++) {
            uint4 v = h4[i];
            t += v.x + v.y + v.z + v.w;
        }
        chunk[tid] = t;
    }
    __syncthreads();
    // inclusive suffix scan over 1024 chunks (Hillis-Steele)
    for (int off = 1; off < 1024; off <<= 1) {
        unsigned v = chunk[tid] + ((tid + off < 1024) ? chunk[tid + off] : 0u);
        __syncthreads();
        chunk[tid] = v;
        __syncthreads();
    }
    // locate crossing chunk, then serial scan of its 64 bins from the top
    {
        unsigned incl = chunk[tid];
        unsigned excl = (tid < 1023) ? chunk[tid + 1] : 0u;
        if (excl < KK && incl >= KK) {
            int kk = KK - (int)excl;
            for (int bin = tid * 64 + 63; bin >= tid * 64; bin--) {
                int c = (int)hist[bin];
                if (kk <= c) { sh_B16 = (unsigned)bin; sh_k1 = kk; break; }
                kk -= c;
            }
        }
    }
    __syncthreads();
    unsigned B16 = sh_B16;

    // ---- consume-and-clear: zero this batch's histogram for next replay ----
    {
        uint4* h4w = reinterpret_cast<uint4*>(hist) + tid * 16;
        uint4 z = make_uint4(0u, 0u, 0u, 0u);
#pragma unroll
        for (int i = 0; i < 16; i++) h4w[i] = z;
    }

    // ---- Stage B pass 1: bits 15..8 among elements with key16 == B16 ----
    if (tid < 256) h256[tid] = 0u;
    __syncthreads();
    for (int i = tid; i < HW; i += 1024) {
        unsigned u = sc[i];
        if ((u >> 16) == B16) atomicAdd(&h256[(u >> 8) & 255u], 1u);
    }
    __syncthreads();
    if (tid == 0) {
        int kk = sh_k1;
        int bin = 255;
        for (; bin > 0; bin--) {
            int c = (int)h256[bin];
            if (kk <= c) break;
            kk -= c;
        }
        sh_T = (B16 << 16) | ((unsigned)bin << 8);
        sh_k2 = kk;
    }
    __syncthreads();
    unsigned P24 = sh_T >> 8;     // 24-bit prefix

    // ---- Stage B pass 2: bits 7..0 among elements with prefix24 == P24 ----
    if (tid < 256) h256[tid] = 0u;
    __syncthreads();
    for (int i = tid; i < HW; i += 1024) {
        unsigned u = sc[i];
        if ((u >> 8) == P24) atomicAdd(&h256[u & 255u], 1u);
    }
    __syncthreads();
    if (tid == 0) {
        int kk = sh_k2;
        int bin = 255;
        for (; bin > 0; bin--) {
            int c = (int)h256[bin];
            if (kk <= c) break;
            kk -= c;
        }
        sh_T = (P24 << 8) | (unsigned)bin;
        sh_needed = kk;
    }
    __syncthreads();
    unsigned T = sh_T;
    int needed = sh_needed;

    // ---- Stage C: sum sims over top-k ----
    float local = 0.0f;
    for (int i = tid; i < HW4; i += 1024) {
        float4 sm = sim4[i];          // independent 128-bit loads, high MLP
        uint4  u  = sc4[i];
#define SEL(f, j) {                                                 \
            unsigned uu = u.f;                                      \
            if (uu > T) {                                           \
                local += sm.j;                                      \
            } else if (uu == T) {                                   \
                int pos = atomicAdd(&sh_tie, 1);                    \
                if (pos < needed) local += sm.j;                    \
            }                                                       \
        }
        SEL(x, x) SEL(y, y) SEL(z, z) SEL(w, w)
#undef SEL
    }

    // block reduction
    for (int off = 16; off > 0; off >>= 1)
        local += __shfl_down_sync(0xFFFFFFFFu, local, off);
    if (lane == 0) red[wid] = local;
    __syncthreads();
    if (wid == 0) {
        float v = red[lane];
        for (int off = 16; off > 0; off >>= 1)
            v += __shfl_down_sync(0xFFFFFFFFu, v, off);
        if (lane == 0) g_bsum[b] = (double)v;
    }

    // ---- fused finalize: last block computes the scalar loss ----
    if (tid == 0) {
        __threadfence();
        unsigned prev = atomicAdd(&g_done, 1u);
        if (prev == BB - 1) {
            g_done = 0;                       // reset for next replay
            double total = 0.0;
            for (int i = 0; i < BB; i++) total += g_bsum[i];
            double mean_sim = total / (double)(BB * KK);
            float align = (float)(1.0 - mean_sim);
            float r1 = 0.f, r2 = 0.f;
            for (int i = 0; i < BB; i++) {
                r1 += dx[i] * dx[i] + dy[i] * dy[i];
                r2 += dt[i] * dt[i];
            }
            float reg = r1 * (1.0f / BB) + r2 * (1.0f / BB);
            out[0] = align + 0.1f * reg;
        }
    }
}

extern "C" void kernel_launch(void* const* d_in, const int* in_sizes, int n_in,
                              void* d_out, int out_size) {
    const float* bev = (const float*)d_in[0];
    const float* pri = (const float*)d_in[1];
    const float* dx  = (const float*)d_in[2];
    const float* dy  = (const float*)d_in[3];
    const float* dt  = (const float*)d_in[4];
    float* out = (float*)d_out;

    k_stats<<<1250, 64>>>(bev, pri);      // 80000 float4-groups, exact

    const int SMEM_SEL = HW * (int)sizeof(unsigned);   // 160000 B
    cudaFuncSetAttribute(k_select_sum,
                         cudaFuncAttributeMaxDynamicSharedMemorySize, SMEM_SEL);
    k_select_sum<<<BB, 1024, SMEM_SEL>>>(dx, dy, dt, out);
}

// round 10
// speedup vs baseline: 1.0661x; 1.0661x over previous
#include <cuda_runtime.h>
#include <cuda_bf16.h>
#include <math.h>

// Problem constants
#define BB   8
#define CC   256
#define HW   40000          // 200*200
#define HW4  10000          // HW / 4
#define KK   8000           // int(0.2 * HW)
#define NB16 65536           // 16-bit key histogram bins

// Scratch (allocation-free rule: __device__ globals)
__device__ unsigned g_score_u[BB * HW];    // float bits of sum(x^2) (>=0: uint order == float order)
__device__ float    g_sim[BB * HW];        // per-pixel cosine similarity
__device__ unsigned g_hist16[BB * NB16];   // per-batch histogram of (score_bits >> 16); zero-init, consume-and-clear
__device__ double   g_bsum[BB];            // per-batch sum of selected sims
__device__ unsigned g_done;                // completion counter (reset by last block)

// ---------------------------------------------------------------------------
// Kernel 1: fused per-pixel channel statistics -> score + cosine sim,
// PLUS a global 16-bit-key score histogram (spread REDG atomics hidden
// under the DRAM-bound stream). grid=1250 x block=64 (104us @ DRAM 80%).
// ---------------------------------------------------------------------------
__global__ void __launch_bounds__(64) k_stats(const float* __restrict__ bev,
                                              const float* __restrict__ pri) {
    int idx = blockIdx.x * 64 + threadIdx.x;   // 1250*64 = 80000 exact
    int b  = idx / HW4;
    int p4 = idx - b * HW4;

    const float4* pb = reinterpret_cast<const float4*>(bev + (size_t)b * CC * HW) + p4;
    const float4* pp = reinterpret_cast<const float4*>(pri + (size_t)b * CC * HW) + p4;

    float4 sb  = {0.f, 0.f, 0.f, 0.f};
    float4 sp  = {0.f, 0.f, 0.f, 0.f};
    float4 sbb = {0.f, 0.f, 0.f, 0.f};
    float4 spp = {0.f, 0.f, 0.f, 0.f};
    float4 sbp = {0.f, 0.f, 0.f, 0.f};

#pragma unroll 4
    for (int c = 0; c < CC; c++) {
        float4 x = __ldg(pb + c * HW4);
        float4 y = __ldg(pp + c * HW4);
#define ACC(f)                                \
        sb.f  += x.f;                         \
        sp.f  += y.f;                         \
        sbb.f  = fmaf(x.f, x.f, sbb.f);       \
        spp.f  = fmaf(y.f, y.f, spp.f);       \
        sbp.f  = fmaf(x.f, y.f, sbp.f);
        ACC(x) ACC(y) ACC(z) ACC(w)
#undef ACC
    }

    const float invC  = 1.0f / (float)CC;
    const float invC1 = 1.0f / (float)(CC - 1);
    int obase = b * HW + p4 * 4;
    unsigned* hist = g_hist16 + b * NB16;

#define EMIT(f, j) {                                                        \
        float Sb = sb.f, Sp = sp.f, Sb2 = sbb.f, Sp2 = spp.f, Sxp = sbp.f;  \
        float SSb = fmaxf(Sb2 - Sb * Sb * invC, 0.0f);                      \
        float SSp = fmaxf(Sp2 - Sp * Sp * invC, 0.0f);                      \
        float Cov = Sxp - Sb * Sp * invC;                                   \
        float sgb = sqrtf(SSb * invC1) + 1e-6f;                             \
        float sgp = sqrtf(SSp * invC1) + 1e-6f;                             \
        float na  = sqrtf(SSb) / sgb;                                       \
        float nb  = sqrtf(SSp) / sgp;                                       \
        float sim = (Cov / (sgb * sgp)) /                                   \
                    (fmaxf(na, 1e-8f) * fmaxf(nb, 1e-8f));                  \
        unsigned su = __float_as_uint(Sb2);                                 \
        g_score_u[obase + j] = su;                                          \
        g_sim[obase + j]     = sim;                                         \
        atomicAdd(&hist[su >> 16], 1u);                                     \
    }
    EMIT(x, 0) EMIT(y, 1) EMIT(z, 2) EMIT(w, 3)
#undef EMIT
}

// ---------------------------------------------------------------------------
// Kernel 2: per-batch exact top-k threshold + sim sum + fused finalize.
// ALL bin searches are parallel suffix scans — R9's 54us came from serial
// single-thread bin walks (64 dependent global loads ~35us + 2x256 dependent
// smem loads ~14us).
// ---------------------------------------------------------------------------
__global__ void __launch_bounds__(1024) k_select_sum(const float* __restrict__ dx,
                                                     const float* __restrict__ dy,
                                                     const float* __restrict__ dt,
                                                     float* __restrict__ out) {
    extern __shared__ unsigned sc[];     // 40000 score words (160 KB)
    int b = blockIdx.x;
    const uint4*  s4   = reinterpret_cast<const uint4*>(g_score_u + b * HW);
    const float4* sim4 = reinterpret_cast<const float4*>(g_sim + b * HW);
    unsigned* hist = g_hist16 + b * NB16;
    uint4* sc4 = reinterpret_cast<uint4*>(sc);

    __shared__ unsigned chunk[1024];     // scan buffer (chunks / bins)
    __shared__ unsigned sbin[64];        // staged bins of the crossing chunk
    __shared__ unsigned h256[256];
    __shared__ unsigned sh_B16, sh_T;
    __shared__ int sh_c, sh_k1, sh_k2, sh_needed, sh_tie;
    __shared__ float red[32];

    const int tid  = threadIdx.x;
    const int lane = tid & 31;
    const int wid  = tid >> 5;

    if (tid == 0) sh_tie = 0;

    // ---- load all scores into smem (coalesced uint4, independent loads) ----
    for (int i = tid; i < HW4; i += 1024)
        sc4[i] = s4[i];

    // ---- Stage A1: chunk sums of the 16-bit histogram (64 bins/thread) ----
    {
        const uint4* h4 = reinterpret_cast<const uint4*>(hist) + tid * 16;
        unsigned t = 0;
#pragma unroll
        for (int i = 0; i < 16; i++) {
            uint4 v = h4[i];
            t += v.x + v.y + v.z + v.w;
        }
        chunk[tid] = t;
    }
    __syncthreads();
    // inclusive suffix scan over 1024 chunks (Hillis-Steele)
    for (int off = 1; off < 1024; off <<= 1) {
        unsigned v = chunk[tid] + ((tid + off < 1024) ? chunk[tid + off] : 0u);
        __syncthreads();
        chunk[tid] = v;
        __syncthreads();
    }
    {
        unsigned incl = chunk[tid];
        unsigned excl = (tid < 1023) ? chunk[tid + 1] : 0u;
        if (excl < KK && incl >= KK) { sh_c = tid; sh_k1 = KK - (int)excl; }
    }
    __syncthreads();

    // ---- Stage A2: parallel refine within the crossing chunk (64 bins) ----
    int cbase = sh_c * 64;
    if (tid < 64) sbin[tid] = hist[cbase + tid];   // 64 parallel loads
    __syncthreads();
    for (int off = 1; off < 64; off <<= 1) {
        unsigned v = 0;
        if (tid < 64) v = sbin[tid] + ((tid + off < 64) ? sbin[tid + off] : 0u);
        __syncthreads();
        if (tid < 64) sbin[tid] = v;
        __syncthreads();
    }
    if (tid < 64) {
        unsigned incl = sbin[tid];
        unsigned excl = (tid < 63) ? sbin[tid + 1] : 0u;
        int k1 = sh_k1;
        if ((int)excl < k1 && (int)incl >= k1) {
            sh_B16 = (unsigned)(cbase + tid);
            sh_k1  = k1 - (int)excl;           // remaining within bin B16
        }
    }
    __syncthreads();
    unsigned B16 = sh_B16;

    // ---- consume-and-clear: zero this batch's histogram for next replay ----
    {
        uint4* h4w = reinterpret_cast<uint4*>(hist) + tid * 16;
        uint4 z = make_uint4(0u, 0u, 0u, 0u);
#pragma unroll
        for (int i = 0; i < 16; i++) h4w[i] = z;
    }

    // ---- Stage B pass 1: bits 15..8 among elements with key16 == B16 ----
    if (tid < 256) h256[tid] = 0u;
    __syncthreads();
    for (int i = tid; i < HW; i += 1024) {
        unsigned u = sc[i];
        if ((u >> 16) == B16) atomicAdd(&h256[(u >> 8) & 255u], 1u);
    }
    __syncthreads();
    for (int off = 1; off < 256; off <<= 1) {   // suffix scan 256
        unsigned v = 0;
        if (tid < 256) v = h256[tid] + ((tid + off < 256) ? h256[tid + off] : 0u);
        __syncthreads();
        if (tid < 256) h256[tid] = v;
        __syncthreads();
    }
    if (tid < 256) {
        unsigned incl = h256[tid];
        unsigned excl = (tid < 255) ? h256[tid + 1] : 0u;
        int k1 = sh_k1;
        if ((int)excl < k1 && (int)incl >= k1) {
            sh_T  = (B16 << 16) | ((unsigned)tid << 8);
            sh_k2 = k1 - (int)excl;
        }
    }
    __syncthreads();
    unsigned P24 = sh_T >> 8;     // 24-bit prefix

    // ---- Stage B pass 2: bits 7..0 among elements with prefix24 == P24 ----
    if (tid < 256) h256[tid] = 0u;
    __syncthreads();
    for (int i = tid; i < HW; i += 1024) {
        unsigned u = sc[i];
        if ((u >> 8) == P24) atomicAdd(&h256[u & 255u], 1u);
    }
    __syncthreads();
    for (int off = 1; off < 256; off <<= 1) {   // suffix scan 256
        unsigned v = 0;
        if (tid < 256) v = h256[tid] + ((tid + off < 256) ? h256[tid + off] : 0u);
        __syncthreads();
        if (tid < 256) h256[tid] = v;
        __syncthreads();
    }
    if (tid < 256) {
        unsigned incl = h256[tid];
        unsigned excl = (tid < 255) ? h256[tid + 1] : 0u;
        int k2 = sh_k2;
        if ((int)excl < k2 && (int)incl >= k2) {
            sh_T      = (P24 << 8) | (unsigned)tid;
            sh_needed = k2 - (int)excl;
        }
    }
    __syncthreads();
    unsigned T = sh_T;
    int needed = sh_needed;

    // ---- Stage C: sum sims over top-k ----
    float local = 0.0f;
    for (int i = tid; i < HW4; i += 1024) {
        float4 sm = sim4[i];          // independent 128-bit loads, high MLP
        uint4  u  = sc4[i];
#define SEL(f, j) {                                                 \
            unsigned uu = u.f;                                      \
            if (uu > T) {                                           \
                local += sm.j;                                      \
            } else if (uu == T) {                                   \
                int pos = atomicAdd(&sh_tie, 1);                    \
                if (pos < needed) local += sm.j;                    \
            }                                                       \
        }
        SEL(x, x) SEL(y, y) SEL(z, z) SEL(w, w)
#undef SEL
    }

    // block reduction
    for (int off = 16; off > 0; off >>= 1)
        local += __shfl_down_sync(0xFFFFFFFFu, local, off);
    if (lane == 0) red[wid] = local;
    __syncthreads();
    if (wid == 0) {
        float v = red[lane];
        for (int off = 16; off > 0; off >>= 1)
            v += __shfl_down_sync(0xFFFFFFFFu, v, off);
        if (lane == 0) g_bsum[b] = (double)v;
    }

    // ---- fused finalize: last block computes the scalar loss ----
    if (tid == 0) {
        __threadfence();
        unsigned prev = atomicAdd(&g_done, 1u);
        if (prev == BB - 1) {
            g_done = 0;                       // reset for next replay
            double total = 0.0;
            for (int i = 0; i < BB; i++) total += g_bsum[i];
            double mean_sim = total / (double)(BB * KK);
            float align = (float)(1.0 - mean_sim);
            float r1 = 0.f, r2 = 0.f;
            for (int i = 0; i < BB; i++) {
                r1 += dx[i] * dx[i] + dy[i] * dy[i];
                r2 += dt[i] * dt[i];
            }
            float reg = r1 * (1.0f / BB) + r2 * (1.0f / BB);
            out[0] = align + 0.1f * reg;
        }
    }
}

extern "C" void kernel_launch(void* const* d_in, const int* in_sizes, int n_in,
                              void* d_out, int out_size) {
    const float* bev = (const float*)d_in[0];
    const float* pri = (const float*)d_in[1];
    const float* dx  = (const float*)d_in[2];
    const float* dy  = (const float*)d_in[3];
    const float* dt  = (const float*)d_in[4];
    float* out = (float*)d_out;

    k_stats<<<1250, 64>>>(bev, pri);      // 80000 float4-groups, exact

    const int SMEM_SEL = HW * (int)sizeof(unsigned);   // 160000 B
    cudaFuncSetAttribute(k_select_sum,
                         cudaFuncAttributeMaxDynamicSharedMemorySize, SMEM_SEL);
    k_select_sum<<<BB, 1024, SMEM_SEL>>>(dx, dy, dt, out);
}